// round 9
// baseline (speedup 1.0000x reference)
#include <cuda_runtime.h>
#include <cuda_bf16.h>
#include <math.h>

#define NQ   10
#define QD   6
#define TPB  256
#define WPB  8          // warps (batch elements) per block
#define FULLM 0xffffffffu

__global__ __launch_bounds__(TPB) void quantumnet_kernel(
    const float* __restrict__ x,        // [B,512]
    const float* __restrict__ Wred,     // [10,512]
    const float* __restrict__ bred,     // [10]
    const float* __restrict__ qparams,  // [150]
    const float* __restrict__ Wpost,    // [2,10]
    const float* __restrict__ bpost,    // [2]
    float* __restrict__ out,            // [B,2]
    int B)
{
    __shared__ float lt[QD][NQ];   // tan(theta/2) per layer-gate
    __shared__ float lcp[QD][NQ];  // cos(theta/2) (deferred-scale product)

    const int t    = threadIdx.x;
    const int lane = t & 31;
    const int wid  = t >> 5;
    const int e    = blockIdx.x * WPB + wid;   // batch element of this warp

    // batch-independent layer-angle tables (threads 0..59)
    if (t < QD * NQ) {
        int k = t / NQ, w = t % NQ;
        float th = qparams[(k + 1) * NQ + w] * 0.5f;
        float c, s;
        sincosf(th, &s, &c);
        lcp[k][w] = c;
        lt[k][w]  = s / c;
    }
    __syncthreads();
    if (e >= B) return;

    // deferred cosine product: true amplitudes = ctot * st ; folded at expval
    float ctot = 1.0f;
    #pragma unroll
    for (int k = 0; k < QD; k++)
        #pragma unroll
        for (int w = 0; w < NQ; w++) ctot *= lcp[k][w];
    const float ctot2 = ctot * ctot;

    // ---- pre-net: pre[q] = x_e . Wred[q] + bred[q]  (warp-local) ---------
    const float4* xb = reinterpret_cast<const float4*>(x + (size_t)e * 512);
    float4 xv[4];
    #pragma unroll
    for (int i = 0; i < 4; i++) xv[i] = xb[lane + 32 * i];

    float g0[NQ], g1[NQ];
    #pragma unroll
    for (int q = 0; q < NQ; q++) {
        const float4* wq = reinterpret_cast<const float4*>(Wred + q * 512);
        float a = 0.0f;
        #pragma unroll
        for (int i = 0; i < 4; i++) {
            float4 wv = wq[lane + 32 * i];
            a += xv[i].x * wv.x + xv[i].y * wv.y + xv[i].z * wv.z + xv[i].w * wv.w;
        }
        #pragma unroll
        for (int o = 16; o > 0; o >>= 1) a += __shfl_xor_sync(FULLM, a, o);
        // q_in = tanh(pre)*pi/2 ; RY uses theta/2 = tanh(pre)*pi/4
        float th = tanhf(a + bred[q]) * 0.78539816339744830962f;
        float c, s;
        sincosf(th, &s, &c);
        g0[q] = c - s;   // amplitude factor for bit=0 (after H then RY on |+>)
        g1[q] = c + s;   // bit=1
    }

    // ---- init product state ---------------------------------------------
    // amplitude index i[9:0]: lane = i[9:5], reg = i[4:0]
    // wire w at bit 9-w: wires 0..4 -> lane bits 4..0, wires 5..9 -> reg bits 4..0
    float st[32];
    {
        float pl = 0.03125f;                       // (1/sqrt2)^10
        pl *= ((lane >> 4) & 1) ? g1[0] : g0[0];
        pl *= ((lane >> 3) & 1) ? g1[1] : g0[1];
        pl *= ((lane >> 2) & 1) ? g1[2] : g0[2];
        pl *= ((lane >> 1) & 1) ? g1[3] : g0[3];
        pl *= ( lane       & 1) ? g1[4] : g0[4];
        #pragma unroll
        for (int r = 0; r < 32; r++) {
            float v = pl;
            v *= ((r >> 4) & 1) ? g1[5] : g0[5];
            v *= ((r >> 3) & 1) ? g1[6] : g0[6];
            v *= ((r >> 2) & 1) ? g1[7] : g0[7];
            v *= ((r >> 1) & 1) ? g1[8] : g0[8];
            v *= ( r       & 1) ? g1[9] : g0[9];
            st[r] = v;
        }
    }

    // Fused double-CNOT permutation, lane/reg decomposition.
    // Verified bit-by-bit (all 10 bits) against pA(pB(i)):
    //   src lane SL = L ^ (L>>1) ^ ((L>>2)&2)          (lane-bits only)
    //   src reg     = G(r) ^ (b<<4), G(r) = r ^ (r>>1) ^ ((r>>2)&5), b = L0^L1
    const int  SL    = lane ^ (lane >> 1) ^ ((lane >> 2) & 2);
    const bool bperm = ((lane ^ (lane >> 1)) & 1) != 0;

    #pragma unroll 1   // body ~9.6KB SASS: fits L0+L1.5 I$; do not unroll
    for (int k = 0; k < QD; k++) {
        // -- CNOT layers (both sub-layers fused): 32 shfl + 32 sel --------
        {
            float f[32];
            #pragma unroll
            for (int u = 0; u < 32; u++) f[u] = __shfl_sync(FULLM, st[u], SL);
            #pragma unroll
            for (int r = 0; r < 32; r++) {
                const int g = r ^ (r >> 1) ^ ((r >> 2) & 5);
                st[r] = bperm ? f[g ^ 16] : f[g];
            }
        }
        // -- RY wires 0..4 (lane bits 4..0): tan form, 1 shfl + 1 fma/word
        //    bit=0 lane: a' = a - t*b ; bit=1 lane: b' = b + t*a
        #pragma unroll
        for (int w = 0; w < 5; w++) {
            const int qb = 4 - w;
            const float tt = lt[k][w];
            const float ts = ((lane >> qb) & 1) ? tt : -tt;
            #pragma unroll
            for (int r = 0; r < 32; r++) {
                float p = __shfl_xor_sync(FULLM, st[r], 1 << qb);
                st[r] = fmaf(ts, p, st[r]);
            }
        }
        // -- RY wires 5..9 (reg bits 4..0): tan form, 1 fma per output ----
        #pragma unroll
        for (int w = 5; w < 10; w++) {
            const int qq = 9 - w;
            const float tt = lt[k][w];
            #pragma unroll
            for (int r0 = 0; r0 < 32; r0++) {
                if (r0 & (1 << qq)) continue;
                const int r1 = r0 | (1 << qq);
                float a  = st[r0];
                float bb = st[r1];
                st[r0] = fmaf(-tt, bb, a);
                st[r1] = fmaf( tt, a, bb);
            }
        }
    }

    // ---- expval Z (rescaled by ctot^2) -----------------------------------
    float tot = 0.0f, sq4 = 0.0f, sq3 = 0.0f, sq2 = 0.0f, sq1 = 0.0f, sq0 = 0.0f;
    #pragma unroll
    for (int r = 0; r < 32; r++) {
        float p = st[r] * st[r];
        tot += p;
        sq4 += ((r >> 4) & 1) ? -p : p;
        sq3 += ((r >> 3) & 1) ? -p : p;
        sq2 += ((r >> 2) & 1) ? -p : p;
        sq1 += ((r >> 1) & 1) ? -p : p;
        sq0 += ( r       & 1) ? -p : p;
    }
    float z[NQ];
    z[0] = ((lane >> 4) & 1) ? -tot : tot;   // wire0 -> lane bit 4
    z[1] = ((lane >> 3) & 1) ? -tot : tot;
    z[2] = ((lane >> 2) & 1) ? -tot : tot;
    z[3] = ((lane >> 1) & 1) ? -tot : tot;
    z[4] = ( lane       & 1) ? -tot : tot;
    z[5] = sq4; z[6] = sq3; z[7] = sq2; z[8] = sq1; z[9] = sq0;
    #pragma unroll
    for (int w = 0; w < NQ; w++) {
        #pragma unroll
        for (int o = 16; o > 0; o >>= 1) z[w] += __shfl_xor_sync(FULLM, z[w], o);
        z[w] *= ctot2;
    }

    // ---- post head -------------------------------------------------------
    if (lane < 2) {
        float s = bpost[lane];
        #pragma unroll
        for (int w = 0; w < NQ; w++) s += Wpost[lane * NQ + w] * z[w];
        out[(size_t)e * 2 + lane] = s;
    }
}

extern "C" void kernel_launch(void* const* d_in, const int* in_sizes, int n_in,
                              void* d_out, int out_size) {
    const float* x       = (const float*)d_in[0];  // input_features [B,512]
    const float* Wred    = (const float*)d_in[1];  // [10,512]
    const float* bred    = (const float*)d_in[2];  // [10]
    const float* qparams = (const float*)d_in[3];  // [150]
    const float* Wpost   = (const float*)d_in[4];  // [2,10]
    const float* bpost   = (const float*)d_in[5];  // [2]
    float* out = (float*)d_out;

    int B = in_sizes[0] / 512;
    int blocks = (B + WPB - 1) / WPB;
    quantumnet_kernel<<<blocks, TPB>>>(x, Wred, bred, qparams, Wpost, bpost, out, B);
}

// round 10
// speedup vs baseline: 1.1237x; 1.1237x over previous
#include <cuda_runtime.h>
#include <cuda_bf16.h>
#include <math.h>

#define NQ   10
#define QD   6
#define TPB  256
#define WPB  8          // warps (batch elements) per block
#define FULLM 0xffffffffu

// ---------------------------------------------------------------------------
// GF(2) matrix A of the fused double-CNOT gather permutation: src = A * dst.
// Column images transcribed from the bit equations verified in earlier rounds:
//   b9=i9, b8=i8^i9, b7=i7^i8, b6=i6^i7^i8, b5=i5^i6, b4=i4^i5^i6,
//   b3=i3^i4, b2=i2^i3^i4, b1=i1^i2, b0=i0^i1^i2
// A = I + N with N strictly downward => N^10 = 0 => A^16 = I => A^-k = A^(16-k).
// ---------------------------------------------------------------------------
__host__ __device__ constexpr unsigned Acol(int b) {
    // column b = set of output bits fed by input bit b
    constexpr unsigned col[10] = {0x001u, 0x003u, 0x007u, 0x00Cu, 0x01Cu,
                                  0x030u, 0x070u, 0x0C0u, 0x1C0u, 0x300u};
    return col[b];
}
__host__ __device__ constexpr unsigned Amul(unsigned m) {
    unsigned r = 0;
    for (int b = 0; b < 10; b++) if ((m >> b) & 1u) r ^= Acol(b);
    return r;
}
__host__ __device__ constexpr unsigned Apow(unsigned m, int k) {
    for (int i = 0; i < k; i++) m = Amul(m);
    return m;
}
// row p of A^k, as a 10-bit mask over input bits
__host__ __device__ constexpr unsigned Arow(int p, int k) {
    unsigned r = 0;
    for (int b = 0; b < 10; b++)
        if ((Apow(1u << b, k) >> p) & 1u) r |= 1u << b;
    return r;
}
__host__ __device__ constexpr unsigned pivotOf(unsigned m) {
    unsigned h = 0;
    for (int b = 0; b < 5; b++) if ((m >> b) & 1u) h = (unsigned)b;
    return 1u << h;
}

// ---------------------------------------------------------------------------
// One RY gate (tan form) on true wire W at layer K, in deferred coordinates.
//   butterfly mask  m = A^K * e_(9-W)   (stored-index pairing)
//   bit functional  f = row_(9-W) of A^(16-K)   (which element has true bit=1)
// Update: st[j] += s * t * st[j^m],  s = <f,j> ? +1 : -1  (tan form; cos deferred)
// ---------------------------------------------------------------------------
template<int K, int W>
__device__ __forceinline__ void ry_wire(float st[32], float t, int lane) {
    constexpr int p = 9 - W;
    constexpr unsigned m  = Apow(1u << p, K);
    constexpr unsigned f  = Arow(p, 16 - K);
    constexpr unsigned mL = m >> 5, mR = m & 31u;
    constexpr unsigned fL = f >> 5, fR = f & 31u;

    // u = sign base from lane part of functional: <f,j> = pl ^ pr ;  s = pr ? -u : u
    float u = (__popc(lane & (int)fL) & 1) ? t : -t;

    if constexpr (mL == 0u) {
        // pure-register butterfly over pairs {r, r^mR}
        constexpr unsigned pv = pivotOf(mR);
        #pragma unroll
        for (int r = 0; r < 32; r++) {
            if (r & (int)pv) continue;
            const int r2 = r ^ (int)mR;
            const float sr = (__popc((unsigned)r & fR) & 1) ? -u : u;
            float a = st[r], b = st[r2];
            st[r]  = fmaf( sr, b, a);   // partner sign is complement (<f,m>=1)
            st[r2] = fmaf(-sr, a, b);
        }
    } else if constexpr (mR == 0u) {
        // pure-lane butterfly: 1 shfl + 1 fma per word
        #pragma unroll
        for (int r = 0; r < 32; r++) {
            const float sr = (__popc((unsigned)r & fR) & 1) ? -u : u;
            float pv = __shfl_xor_sync(FULLM, st[r], (int)mL);
            st[r] = fmaf(sr, pv, st[r]);
        }
    } else {
        // mixed mask: partner of (L,r) is (L^mL, r^mR); process reg-pairs
        // together so all shfl reads complete before the writes (no temp array)
        constexpr unsigned pv = pivotOf(mR);
        #pragma unroll
        for (int r = 0; r < 32; r++) {
            if (r & (int)pv) continue;
            const int r2 = r ^ (int)mR;
            const float sr  = (__popc((unsigned)r  & fR) & 1) ? -u : u;
            const float sr2 = (__popc((unsigned)r2 & fR) & 1) ? -u : u;
            float pa = __shfl_xor_sync(FULLM, st[r2], (int)mL);
            float pb = __shfl_xor_sync(FULLM, st[r],  (int)mL);
            st[r]  = fmaf(sr,  pa, st[r]);
            st[r2] = fmaf(sr2, pb, st[r2]);
        }
    }
}

template<int K, int W = 0>
__device__ __forceinline__ void ry_layer(float st[32], const float* ltk, int lane) {
    if constexpr (W < NQ) {
        ry_wire<K, W>(st, ltk[W], lane);
        ry_layer<K, W + 1>(st, ltk, lane);
    }
}

template<int K = 1>
__device__ __forceinline__ void all_layers(float st[32], const float (*lt)[NQ], int lane) {
    if constexpr (K <= QD) {
        // CNOT permutation of layer K is deferred (T <- T*A): zero data movement
        ry_layer<K>(st, lt[K - 1], lane);
        all_layers<K + 1>(st, lt, lane);
    }
}

// expval accumulator for wire W: functional g = row_(9-W) of A^-6 = A^10
template<int W>
__device__ __forceinline__ float zacc(const float p2[32]) {
    constexpr unsigned gR = Arow(9 - W, 10) & 31u;
    float acc = 0.0f;
    #pragma unroll
    for (int r = 0; r < 32; r++)
        acc += (__popc((unsigned)r & gR) & 1) ? -p2[r] : p2[r];
    return acc;
}

__global__ __launch_bounds__(TPB) void quantumnet_kernel(
    const float* __restrict__ x,        // [B,512]
    const float* __restrict__ Wred,     // [10,512]
    const float* __restrict__ bred,     // [10]
    const float* __restrict__ qparams,  // [150]
    const float* __restrict__ Wpost,    // [2,10]
    const float* __restrict__ bpost,    // [2]
    float* __restrict__ out,            // [B,2]
    int B)
{
    __shared__ float lt[QD][NQ];   // tan(theta/2) per layer-gate
    __shared__ float lcp[QD][NQ];  // cos(theta/2) (deferred-scale product)

    const int t    = threadIdx.x;
    const int lane = t & 31;
    const int wid  = t >> 5;
    const int e    = blockIdx.x * WPB + wid;   // batch element of this warp

    // batch-independent layer-angle tables (threads 0..59)
    if (t < QD * NQ) {
        int k = t / NQ, w = t % NQ;
        float th = qparams[(k + 1) * NQ + w] * 0.5f;
        float c, s;
        sincosf(th, &s, &c);
        lcp[k][w] = c;
        lt[k][w]  = s / c;
    }
    __syncthreads();
    if (e >= B) return;

    // deferred cosine product: true amplitudes = ctot * st ; folded at expval
    float ctot = 1.0f;
    #pragma unroll
    for (int k = 0; k < QD; k++)
        #pragma unroll
        for (int w = 0; w < NQ; w++) ctot *= lcp[k][w];
    const float ctot2 = ctot * ctot;

    // ---- pre-net: pre[q] = x_e . Wred[q] + bred[q]  (warp-local) ---------
    const float4* xb = reinterpret_cast<const float4*>(x + (size_t)e * 512);
    float4 xv[4];
    #pragma unroll
    for (int i = 0; i < 4; i++) xv[i] = xb[lane + 32 * i];

    float g0[NQ], g1[NQ];
    #pragma unroll
    for (int q = 0; q < NQ; q++) {
        const float4* wq = reinterpret_cast<const float4*>(Wred + q * 512);
        float a = 0.0f;
        #pragma unroll
        for (int i = 0; i < 4; i++) {
            float4 wv = wq[lane + 32 * i];
            a += xv[i].x * wv.x + xv[i].y * wv.y + xv[i].z * wv.z + xv[i].w * wv.w;
        }
        #pragma unroll
        for (int o = 16; o > 0; o >>= 1) a += __shfl_xor_sync(FULLM, a, o);
        // q_in = tanh(pre)*pi/2 ; RY uses theta/2 = tanh(pre)*pi/4
        float th = tanhf(a + bred[q]) * 0.78539816339744830962f;
        float c, s;
        sincosf(th, &s, &c);
        g0[q] = c - s;   // amplitude factor for bit=0 (after H then RY on |+>)
        g1[q] = c + s;   // bit=1
    }

    // ---- init product state (T = I at this point) ------------------------
    // amplitude index i[9:0]: lane = i[9:5], reg = i[4:0]
    // wire w at bit 9-w: wires 0..4 -> lane bits 4..0, wires 5..9 -> reg bits 4..0
    float st[32];
    {
        float pl = 0.03125f;                       // (1/sqrt2)^10
        pl *= ((lane >> 4) & 1) ? g1[0] : g0[0];
        pl *= ((lane >> 3) & 1) ? g1[1] : g0[1];
        pl *= ((lane >> 2) & 1) ? g1[2] : g0[2];
        pl *= ((lane >> 1) & 1) ? g1[3] : g0[3];
        pl *= ( lane       & 1) ? g1[4] : g0[4];
        #pragma unroll
        for (int r = 0; r < 32; r++) {
            float v = pl;
            v *= ((r >> 4) & 1) ? g1[5] : g0[5];
            v *= ((r >> 3) & 1) ? g1[6] : g0[6];
            v *= ((r >> 2) & 1) ? g1[7] : g0[7];
            v *= ((r >> 1) & 1) ? g1[8] : g0[8];
            v *= ( r       & 1) ? g1[9] : g0[9];
            st[r] = v;
        }
    }

    // ---- 6 entangling layers, CNOT permutations deferred into coordinates -
    all_layers<1>(st, lt, lane);

    // ---- expval Z in deferred coordinates: true[i] = stored[A^6 i] -------
    // <Z_w> = sum_j (-1)^(<row_(9-w) A^10, j>) |stored[j]|^2
    #pragma unroll
    for (int r = 0; r < 32; r++) st[r] *= st[r];   // st now holds |amp|^2

    float z[NQ];
    z[0] = zacc<0>(st); z[1] = zacc<1>(st); z[2] = zacc<2>(st);
    z[3] = zacc<3>(st); z[4] = zacc<4>(st); z[5] = zacc<5>(st);
    z[6] = zacc<6>(st); z[7] = zacc<7>(st); z[8] = zacc<8>(st);
    z[9] = zacc<9>(st);

    // lane part of each functional, then warp-reduce and rescale
    {
        constexpr unsigned gl[NQ] = {
            Arow(9, 10) >> 5, Arow(8, 10) >> 5, Arow(7, 10) >> 5,
            Arow(6, 10) >> 5, Arow(5, 10) >> 5, Arow(4, 10) >> 5,
            Arow(3, 10) >> 5, Arow(2, 10) >> 5, Arow(1, 10) >> 5,
            Arow(0, 10) >> 5 };
        #pragma unroll
        for (int w = 0; w < NQ; w++) {
            float v = (__popc(lane & (int)gl[w]) & 1) ? -z[w] : z[w];
            #pragma unroll
            for (int o = 16; o > 0; o >>= 1) v += __shfl_xor_sync(FULLM, v, o);
            z[w] = v * ctot2;
        }
    }

    // ---- post head -------------------------------------------------------
    if (lane < 2) {
        float s = bpost[lane];
        #pragma unroll
        for (int w = 0; w < NQ; w++) s += Wpost[lane * NQ + w] * z[w];
        out[(size_t)e * 2 + lane] = s;
    }
}

extern "C" void kernel_launch(void* const* d_in, const int* in_sizes, int n_in,
                              void* d_out, int out_size) {
    const float* x       = (const float*)d_in[0];  // input_features [B,512]
    const float* Wred    = (const float*)d_in[1];  // [10,512]
    const float* bred    = (const float*)d_in[2];  // [10]
    const float* qparams = (const float*)d_in[3];  // [150]
    const float* Wpost   = (const float*)d_in[4];  // [2,10]
    const float* bpost   = (const float*)d_in[5];  // [2]
    float* out = (float*)d_out;

    int B = in_sizes[0] / 512;
    int blocks = (B + WPB - 1) / WPB;
    quantumnet_kernel<<<blocks, TPB>>>(x, Wred, bred, qparams, Wpost, bpost, out, B);
}